// round 9
// baseline (speedup 1.0000x reference)
#include <cuda_runtime.h>
#include <math.h>
#include <stdint.h>

// Problem constants
#define NE 32
#define NT 2048
#define NH 1024
#define NI 512
#define NK 4
#define NP (NT*NK)   // 8192 routed pairs

#define BM 128
#define BN 64
#define BK 16
#define MAXT 96      // max row-tiles across all experts

// ---- scratch (device globals) ----
__device__ int g_off[NE+1];
__device__ int g_count[NE];
__device__ int g_cursor[NE];
__device__ int g_tok[NP];
__device__ int g_slot[NP];
__device__ float g_wt[NP];
__device__ int g_tile_e[MAXT];
__device__ int g_tile_r[MAXT];
__device__ int g_ntile;
__device__ __align__(16) float g_h[(size_t)NP * NI];     // tf32-grid h, 16 MB
__device__ __align__(16) float g_outp[(size_t)NP * NH];  // 32 MB

// ---------------- PTX helpers ----------------
__device__ __forceinline__ float f2tf_f(float f) {
    uint32_t r; asm("cvt.rna.tf32.f32 %0, %1;\n" : "=r"(r) : "f"(f));
    return __uint_as_float(r);
}
__device__ __forceinline__ float4 round4(float4 v) {
    v.x = f2tf_f(v.x); v.y = f2tf_f(v.y); v.z = f2tf_f(v.z); v.w = f2tf_f(v.w);
    return v;
}
// Operands are pre-rounded to the tf32 grid, so raw fp32 bit patterns are
// already exact tf32 values -> no cvt in the inner loop.
__device__ __forceinline__ void mma_tf32(float c[4], const uint32_t a[4],
                                         uint32_t b0, uint32_t b1) {
    asm volatile(
        "mma.sync.aligned.m16n8k8.row.col.f32.tf32.tf32.f32 "
        "{%0,%1,%2,%3}, {%4,%5,%6,%7}, {%8,%9}, {%0,%1,%2,%3};\n"
        : "+f"(c[0]), "+f"(c[1]), "+f"(c[2]), "+f"(c[3])
        : "r"(a[0]), "r"(a[1]), "r"(a[2]), "r"(a[3]), "r"(b0), "r"(b1));
}

// ---------------------------------------------------------------------------
// Routing (counting sort by expert + tile list). Atomic order within an
// expert is non-deterministic but position-independent; final reduce is in
// fixed slot order -> deterministic output.
// ---------------------------------------------------------------------------
__global__ void route_kernel(const int* __restrict__ idx, const float* __restrict__ tw) {
    int tid = threadIdx.x;
    if (tid < NE) { g_count[tid] = 0; g_cursor[tid] = 0; }
    __syncthreads();
    for (int i = tid; i < NP; i += blockDim.x)
        atomicAdd(&g_count[idx[i]], 1);
    __syncthreads();
    if (tid == 0) {
        int s = 0, nt = 0;
        for (int e = 0; e < NE; e++) {
            g_off[e] = s;
            int c = g_count[e];
            for (int r0 = 0; r0 < c; r0 += BM) { g_tile_e[nt] = e; g_tile_r[nt] = r0; nt++; }
            s += c;
        }
        g_off[NE] = s;
        g_ntile = nt;
    }
    __syncthreads();
    for (int i = tid; i < NP; i += blockDim.x) {
        int e = idx[i];
        int p = g_off[e] + atomicAdd(&g_cursor[e], 1);
        g_tok[p]  = i >> 2;
        g_slot[p] = i;
        g_wt[p]   = tw[i];
    }
}

// ---------------------------------------------------------------------------
// GEMM1: gathered tokens x gate_up^T (tf32 mma.sync), fused silu*up.
// 128x(64g+64u) CTA tile, BK=16, register-double-buffered LDG->rna->STS fill.
// ---------------------------------------------------------------------------
__global__ __launch_bounds__(256) void gemm1_kernel(
    const float* __restrict__ X, const float* __restrict__ W)
{
    int by = blockIdx.y;
    if (by >= g_ntile) return;
    int e = g_tile_e[by], row0 = g_tile_r[by];
    int n0 = g_off[e], ne = g_off[e+1] - n0;
    int col0 = blockIdx.x * BN;

    __shared__ __align__(16) float sX[2][BM][BK+4];
    __shared__ __align__(16) float sG[2][BN][BK+4];
    __shared__ __align__(16) float sU[2][BN][BK+4];

    int tid = threadIdx.x;
    int arow = tid >> 1, acol = (tid & 1) * 8;
    int grow = row0 + arow;
    int tok = g_tok[n0 + (grow < ne ? grow : 0)];
    const float* pA = X + (size_t)tok * NH + acol;
    int brow = tid >> 2, bcol = (tid & 3) * 4;
    const float* Wg = W + (size_t)e * (2*NI) * NH;
    const float* pG = Wg + (size_t)(col0 + brow) * NH + bcol;
    const float* pU = Wg + (size_t)(NI + col0 + brow) * NH + bcol;

    int wid = tid >> 5, lane = tid & 31;
    int wm = (wid & 3) * 32, wn = (wid >> 2) * 32;
    int gid = lane >> 2, tig = lane & 3;

    float ag[2][4][4] = {}, au[2][4][4] = {};
    float4 ra0, ra1, rg, ru;

    #define G1_LDG(kk) do { \
        ra0 = *(const float4*)(pA + (kk)); \
        ra1 = *(const float4*)(pA + (kk) + 4); \
        rg  = *(const float4*)(pG + (kk)); \
        ru  = *(const float4*)(pU + (kk)); \
    } while (0)
    #define G1_STS(s) do { \
        *(float4*)&sX[s][arow][acol]   = round4(ra0); \
        *(float4*)&sX[s][arow][acol+4] = round4(ra1); \
        *(float4*)&sG[s][brow][bcol]   = round4(rg); \
        *(float4*)&sU[s][brow][bcol]   = round4(ru); \
    } while (0)

    const int NIT = NH / BK;   // 64
    G1_LDG(0); G1_STS(0);
    __syncthreads();

    for (int it = 0; it < NIT; it++) {
        if (it + 1 < NIT) G1_LDG((it+1) * BK);
        int s = it & 1;
        #pragma unroll
        for (int k8 = 0; k8 < 2; k8++) {
            int ko = k8*8 + tig;
            uint32_t a[2][4];
            #pragma unroll
            for (int i = 0; i < 2; i++) {
                int r = wm + i*16 + gid;
                a[i][0] = __float_as_uint(sX[s][r  ][ko  ]);
                a[i][1] = __float_as_uint(sX[s][r+8][ko  ]);
                a[i][2] = __float_as_uint(sX[s][r  ][ko+4]);
                a[i][3] = __float_as_uint(sX[s][r+8][ko+4]);
            }
            #pragma unroll
            for (int j = 0; j < 4; j++) {
                int n = wn + j*8 + gid;
                uint32_t bg0 = __float_as_uint(sG[s][n][ko]);
                uint32_t bg1 = __float_as_uint(sG[s][n][ko+4]);
                uint32_t bu0 = __float_as_uint(sU[s][n][ko]);
                uint32_t bu1 = __float_as_uint(sU[s][n][ko+4]);
                #pragma unroll
                for (int i = 0; i < 2; i++) {
                    mma_tf32(ag[i][j], a[i], bg0, bg1);
                    mma_tf32(au[i][j], a[i], bu0, bu1);
                }
            }
        }
        if (it + 1 < NIT) G1_STS((it+1) & 1);
        __syncthreads();
    }

    // Epilogue: silu(gate)*up, rounded onto tf32 grid so GEMM2 needs no cvt.
    #pragma unroll
    for (int i = 0; i < 2; i++) {
        #pragma unroll
        for (int h = 0; h < 2; h++) {
            int r = row0 + wm + i*16 + gid + h*8;
            if (r >= ne) continue;
            size_t rb = (size_t)(n0 + r) * NI + col0 + wn + 2*tig;
            #pragma unroll
            for (int j = 0; j < 4; j++) {
                float g0 = ag[i][j][h*2], g1 = ag[i][j][h*2+1];
                float u0 = au[i][j][h*2], u1 = au[i][j][h*2+1];
                float v0 = f2tf_f(g0 / (1.f + __expf(-g0)) * u0);
                float v1 = f2tf_f(g1 / (1.f + __expf(-g1)) * u1);
                *(float2*)&g_h[rb + j*8] = make_float2(v0, v1);
            }
        }
    }
}

// ---------------------------------------------------------------------------
// GEMM2: h @ down^T (tf32 mma.sync), scaled by routing weight, slot-scattered.
// ---------------------------------------------------------------------------
__global__ __launch_bounds__(256) void gemm2_kernel(const float* __restrict__ Wd)
{
    int by = blockIdx.y;
    if (by >= g_ntile) return;
    int e = g_tile_e[by], row0 = g_tile_r[by];
    int n0 = g_off[e], ne = g_off[e+1] - n0;
    int col0 = blockIdx.x * BN;

    __shared__ __align__(16) float sH[2][BM][BK+4];
    __shared__ __align__(16) float sW[2][BN][BK+4];

    int tid = threadIdx.x;
    int arow = tid >> 1, acol = (tid & 1) * 8;
    int grow = row0 + arow;
    const float* pA = g_h + (size_t)(n0 + (grow < ne ? grow : 0)) * NI + acol;
    int brow = tid >> 2, bcol = (tid & 3) * 4;
    const float* pB = Wd + (size_t)e * NH * NI + (size_t)(col0 + brow) * NI + bcol;

    int wid = tid >> 5, lane = tid & 31;
    int wm = (wid & 3) * 32, wn = (wid >> 2) * 32;
    int gid = lane >> 2, tig = lane & 3;

    float acc[2][4][4] = {};
    float4 ra0, ra1, rb;

    // A (g_h) is already on the tf32 grid -> no rounding needed; B needs it.
    #define G2_LDG(kk) do { \
        ra0 = *(const float4*)(pA + (kk)); \
        ra1 = *(const float4*)(pA + (kk) + 4); \
        rb  = *(const float4*)(pB + (kk)); \
    } while (0)
    #define G2_STS(s) do { \
        *(float4*)&sH[s][arow][acol]   = ra0; \
        *(float4*)&sH[s][arow][acol+4] = ra1; \
        *(float4*)&sW[s][brow][bcol]   = round4(rb); \
    } while (0)

    const int NIT = NI / BK;   // 32
    G2_LDG(0); G2_STS(0);
    __syncthreads();

    for (int it = 0; it < NIT; it++) {
        if (it + 1 < NIT) G2_LDG((it+1) * BK);
        int s = it & 1;
        #pragma unroll
        for (int k8 = 0; k8 < 2; k8++) {
            int ko = k8*8 + tig;
            uint32_t a[2][4];
            #pragma unroll
            for (int i = 0; i < 2; i++) {
                int r = wm + i*16 + gid;
                a[i][0] = __float_as_uint(sH[s][r  ][ko  ]);
                a[i][1] = __float_as_uint(sH[s][r+8][ko  ]);
                a[i][2] = __float_as_uint(sH[s][r  ][ko+4]);
                a[i][3] = __float_as_uint(sH[s][r+8][ko+4]);
            }
            #pragma unroll
            for (int j = 0; j < 4; j++) {
                int n = wn + j*8 + gid;
                uint32_t b0 = __float_as_uint(sW[s][n][ko]);
                uint32_t b1 = __float_as_uint(sW[s][n][ko+4]);
                #pragma unroll
                for (int i = 0; i < 2; i++)
                    mma_tf32(acc[i][j], a[i], b0, b1);
            }
        }
        if (it + 1 < NIT) G2_STS((it+1) & 1);
        __syncthreads();
    }

    #pragma unroll
    for (int i = 0; i < 2; i++) {
        #pragma unroll
        for (int h = 0; h < 2; h++) {
            int r = row0 + wm + i*16 + gid + h*8;
            if (r >= ne) continue;
            int p = n0 + r;
            float w = g_wt[p];
            size_t rb2 = (size_t)g_slot[p] * NH + col0 + wn + 2*tig;
            #pragma unroll
            for (int j = 0; j < 4; j++) {
                float v0 = w * acc[i][j][h*2];
                float v1 = w * acc[i][j][h*2+1];
                *(float2*)&g_outp[rb2 + j*8] = make_float2(v0, v1);
            }
        }
    }
}

// ---------------------------------------------------------------------------
// Deterministic per-token reduction over the 4 slots (fixed order).
// ---------------------------------------------------------------------------
__global__ void reduce_kernel(float* __restrict__ out) {
    int idx4 = blockIdx.x * blockDim.x + threadIdx.x;
    if (idx4 >= NT * NH / 4) return;
    int t  = idx4 / (NH/4);
    int h4 = idx4 % (NH/4);
    float4 s = make_float4(0.f, 0.f, 0.f, 0.f);
    #pragma unroll
    for (int k = 0; k < NK; k++) {
        const float4 v = *(const float4*)&g_outp[(size_t)(t*NK + k) * NH + h4*4];
        s.x += v.x; s.y += v.y; s.z += v.z; s.w += v.w;
    }
    *(float4*)&out[(size_t)t * NH + h4*4] = s;
}

// ---------------------------------------------------------------------------
extern "C" void kernel_launch(void* const* d_in, const int* in_sizes, int n_in,
                              void* d_out, int out_size)
{
    const float* X    = (const float*)d_in[0];
    const int*   idx  = (const int*)  d_in[1];
    const float* tw   = (const float*)d_in[2];
    const float* gup  = (const float*)d_in[3];
    const float* down = (const float*)d_in[4];
    float* out = (float*)d_out;

    route_kernel<<<1, 256>>>(idx, tw);
    gemm1_kernel<<<dim3(NI/BN, MAXT), 256>>>(X, gup);
    gemm2_kernel<<<dim3(NH/BN, MAXT), 256>>>(down);
    reduce_kernel<<<(NT*NH/4 + 255)/256, 256>>>(out);
}

// round 15
// speedup vs baseline: 1.2612x; 1.2612x over previous
#include <cuda_runtime.h>
#include <cuda_fp16.h>
#include <math.h>
#include <stdint.h>

// Problem constants
#define NE 32
#define NT 2048
#define NH 1024
#define NI 512
#define NK 4
#define NP (NT*NK)   // 8192 routed pairs

#define BM 128
#define BK 32
#define MAXT 96

#define PITCHB 80                    // bytes per smem row (64B data + 16B pad)
#define STG    (BM*PITCHB)           // 10240 B per operand tile
#define STAGE  (2*STG)               // A+B per stage
#define SMEM_BYTES (2*STAGE)         // 40960 B (2 stages); epilogue reuses it

// ---- scratch (device globals) ----
__device__ int g_off[NE+1];
__device__ int g_count[NE];
__device__ int g_cursor[NE];
__device__ int g_tok[NP];
__device__ int g_slot[NP];
__device__ float g_wt[NP];
__device__ int g_tile_e[MAXT];
__device__ int g_tile_r[MAXT];
__device__ int g_ntile;
__device__ __align__(16) __half g_Xh[(size_t)NT*NH];          // 4 MB
__device__ __align__(16) __half g_guph[(size_t)NE*2*NI*NH];   // 64 MB
__device__ __align__(16) __half g_downh[(size_t)NE*NH*NI];    // 32 MB
__device__ __align__(16) __half g_hh[(size_t)NP*NI];          // 8 MB
__device__ __align__(16) float  g_outp[(size_t)NP*NH];        // 32 MB

// ---------------- PTX helpers ----------------
__device__ __forceinline__ void ldsm4(uint32_t* r, uint32_t a) {
    asm volatile("ldmatrix.sync.aligned.m8n8.x4.shared.b16 {%0,%1,%2,%3}, [%4];"
        : "=r"(r[0]), "=r"(r[1]), "=r"(r[2]), "=r"(r[3]) : "r"(a));
}
__device__ __forceinline__ void mma_f16(float c[4], const uint32_t a[4],
                                        uint32_t b0, uint32_t b1) {
    asm volatile(
        "mma.sync.aligned.m16n8k16.row.col.f32.f16.f16.f32 "
        "{%0,%1,%2,%3}, {%4,%5,%6,%7}, {%8,%9}, {%0,%1,%2,%3};\n"
        : "+f"(c[0]), "+f"(c[1]), "+f"(c[2]), "+f"(c[3])
        : "r"(a[0]), "r"(a[1]), "r"(a[2]), "r"(a[3]), "r"(b0), "r"(b1));
}
__device__ __forceinline__ void cp16(uint32_t smem_addr, const void* gmem) {
    asm volatile("cp.async.cg.shared.global [%0], [%1], 16;\n" :: "r"(smem_addr), "l"(gmem));
}
#define CP_COMMIT asm volatile("cp.async.commit_group;\n")
#define CP_WAIT1  asm volatile("cp.async.wait_group 1;\n" ::: "memory")
#define CP_WAIT0  asm volatile("cp.async.wait_group 0;\n" ::: "memory")
__device__ __forceinline__ uint32_t s2u(const void* p) {
    uint32_t a; asm("{ .reg .u64 t; cvta.to.shared.u64 t, %1; cvt.u32.u64 %0, t; }"
                    : "=r"(a) : "l"(p)); return a;
}
__device__ __forceinline__ uint32_t h2_bits(__half2 h) {
    union { __half2 h; uint32_t u; } c; c.h = h; return c.u;
}

// ---------------- fp32 -> fp16 conversion (rn) ----------------
__global__ void cvt_kernel(const float4* __restrict__ src, uint4* __restrict__ dst, int n8) {
    int i = blockIdx.x * blockDim.x + threadIdx.x;
    if (i >= n8) return;
    float4 v0 = src[2*i], v1 = src[2*i+1];
    uint4 o;
    o.x = h2_bits(__floats2half2_rn(v0.x, v0.y));
    o.y = h2_bits(__floats2half2_rn(v0.z, v0.w));
    o.z = h2_bits(__floats2half2_rn(v1.x, v1.y));
    o.w = h2_bits(__floats2half2_rn(v1.z, v1.w));
    dst[i] = o;
}

// ---------------- routing ----------------
__global__ void route_kernel(const int* __restrict__ idx, const float* __restrict__ tw) {
    int tid = threadIdx.x;
    if (tid < NE) { g_count[tid] = 0; g_cursor[tid] = 0; }
    __syncthreads();
    for (int i = tid; i < NP; i += blockDim.x)
        atomicAdd(&g_count[idx[i]], 1);
    __syncthreads();
    if (tid == 0) {
        int s = 0, nt = 0;
        for (int e = 0; e < NE; e++) {
            g_off[e] = s;
            int c = g_count[e];
            for (int r0 = 0; r0 < c; r0 += BM) { g_tile_e[nt] = e; g_tile_r[nt] = r0; nt++; }
            s += c;
        }
        g_off[NE] = s;
        g_ntile = nt;
    }
    __syncthreads();
    for (int i = tid; i < NP; i += blockDim.x) {
        int e = idx[i];
        int p = g_off[e] + atomicAdd(&g_cursor[e], 1);
        g_tok[p]  = i >> 2;
        g_slot[p] = i;
        g_wt[p]   = tw[i];
    }
}

// ---------------------------------------------------------------------------
// GEMM1 (fp16 mma.sync m16n8k16 + ldmatrix): 128 rows x [64 gate | 64 up].
// ---------------------------------------------------------------------------
__global__ __launch_bounds__(256, 2) void gemm1_kernel(void)
{
    int by = blockIdx.y;
    if (by >= g_ntile) return;
    __shared__ __align__(16) uint8_t smem[SMEM_BYTES];

    int e = g_tile_e[by], row0 = g_tile_r[by];
    int n0 = g_off[e], ne = g_off[e+1] - n0;
    int col0 = blockIdx.x * 64;

    uint32_t sb = s2u(smem);
    int tid = threadIdx.x;
    int wid = tid >> 5, lane = tid & 31;

    // loaders: tid<128 -> A (token rows), tid>=128 -> B (64 gate + 64 up rows)
    bool isB = tid >= 128;
    int lrow = tid & 127;
    const __half* lsrc;
    if (!isB) {
        int rr = row0 + lrow;
        int tok = g_tok[n0 + (rr < ne ? rr : 0)];
        lsrc = g_Xh + (size_t)tok * NH;
    } else {
        const __half* Wg = g_guph + (size_t)e * (2*NI) * NH;
        lsrc = (lrow < 64) ? Wg + (size_t)(col0 + lrow) * NH
                           : Wg + (size_t)(NI + col0 + (lrow - 64)) * NH;
    }
    uint32_t ldst = sb + (isB ? STG : 0) + (uint32_t)lrow * PITCHB;

    #define ISSUE(s, kk) do { \
        uint32_t d = ldst + (s)*STAGE; \
        const __half* p = lsrc + (kk); \
        cp16(d,      p); cp16(d+16, p+8); cp16(d+32, p+16); cp16(d+48, p+24); \
        CP_COMMIT; \
    } while (0)

    int wm = (wid & 3) * 32;          // warp M offset
    int half = wid >> 2;              // 0 = gate cols, 1 = up cols
    int bn0 = half * 64;              // B smem row base for this warp
    int gid = lane >> 2, tig = lane & 3;
    uint32_t lmoff = (uint32_t)(lane & 15) * PITCHB + (uint32_t)(lane >> 4) * 16;

    float acc[2][8][4] = {};

    const int NIT = NH / BK;   // 32
    ISSUE(0, 0);

    for (int it = 0; it < NIT; it++) {
        if (it + 1 < NIT) { ISSUE((it+1)&1, (it+1)*BK); CP_WAIT1; }
        else              { CP_WAIT0; }
        __syncthreads();
        uint32_t sA = sb + (it&1)*STAGE;
        uint32_t sB = sA + STG;
        #pragma unroll
        for (int ks = 0; ks < 2; ks++) {
            uint32_t a[2][4];
            #pragma unroll
            for (int i = 0; i < 2; i++)
                ldsm4(a[i], sA + (uint32_t)(wm + i*16)*PITCHB + ks*32 + lmoff);
            #pragma unroll
            for (int jp = 0; jp < 4; jp++) {
                uint32_t b[4];
                ldsm4(b, sB + (uint32_t)(bn0 + jp*16)*PITCHB + ks*32 + lmoff);
                mma_f16(acc[0][2*jp  ], a[0], b[0], b[2]);
                mma_f16(acc[1][2*jp  ], a[1], b[0], b[2]);
                mma_f16(acc[0][2*jp+1], a[0], b[1], b[3]);
                mma_f16(acc[1][2*jp+1], a[1], b[1], b[3]);
            }
        }
        __syncthreads();
    }

    // Epilogue: exchange up-half via smem, gate warps compute silu(g)*u -> g_hh
    float* ex = (float*)smem;          // 128 x 66 floats = 33.8 KB (< 40 KB)
    if (half == 1) {
        #pragma unroll
        for (int i = 0; i < 2; i++) {
            int rb = (wid & 3)*32 + i*16 + gid;
            #pragma unroll
            for (int j = 0; j < 8; j++) {
                ex[(rb  )*66 + j*8 + 2*tig    ] = acc[i][j][0];
                ex[(rb  )*66 + j*8 + 2*tig + 1] = acc[i][j][1];
                ex[(rb+8)*66 + j*8 + 2*tig    ] = acc[i][j][2];
                ex[(rb+8)*66 + j*8 + 2*tig + 1] = acc[i][j][3];
            }
        }
    }
    __syncthreads();
    if (half == 0) {
        #pragma unroll
        for (int i = 0; i < 2; i++) {
            #pragma unroll
            for (int h = 0; h < 2; h++) {
                int rl = (wid & 3)*32 + i*16 + gid + h*8;
                int r = row0 + rl;
                if (r >= ne) continue;
                __half* dst = g_hh + (size_t)(n0 + r) * NI + col0;
                #pragma unroll
                for (int j = 0; j < 8; j++) {
                    float g0 = acc[i][j][h*2],   u0 = ex[rl*66 + j*8 + 2*tig];
                    float g1 = acc[i][j][h*2+1], u1 = ex[rl*66 + j*8 + 2*tig + 1];
                    float v0 = g0 / (1.f + __expf(-g0)) * u0;
                    float v1 = g1 / (1.f + __expf(-g1)) * u1;
                    *(__half2*)&dst[j*8 + 2*tig] = __floats2half2_rn(v0, v1);
                }
            }
        }
    }
}

// ---------------------------------------------------------------------------
// GEMM2 (fp16): h @ down^T, 128 rows x 128 H cols, scaled, slot-scattered.
// ---------------------------------------------------------------------------
__global__ __launch_bounds__(256, 2) void gemm2_kernel(void)
{
    int by = blockIdx.y;
    if (by >= g_ntile) return;
    __shared__ __align__(16) uint8_t smem[SMEM_BYTES];

    int e = g_tile_e[by], row0 = g_tile_r[by];
    int n0 = g_off[e], ne = g_off[e+1] - n0;
    int col0 = blockIdx.x * 128;

    uint32_t sb = s2u(smem);
    int tid = threadIdx.x;
    int wid = tid >> 5, lane = tid & 31;

    bool isB = tid >= 128;
    int lrow = tid & 127;
    const __half* lsrc;
    if (!isB) {
        int rr = row0 + lrow;
        lsrc = g_hh + (size_t)(n0 + (rr < ne ? rr : 0)) * NI;
    } else {
        lsrc = g_downh + (size_t)e * NH * NI + (size_t)(col0 + lrow) * NI;
    }
    uint32_t ldst = sb + (isB ? STG : 0) + (uint32_t)lrow * PITCHB;

    int wm = (wid & 3) * 32;
    int bn0 = (wid >> 2) * 64;
    int gid = lane >> 2, tig = lane & 3;
    uint32_t lmoff = (uint32_t)(lane & 15) * PITCHB + (uint32_t)(lane >> 4) * 16;

    float acc[2][8][4] = {};

    const int NIT = NI / BK;   // 16
    ISSUE(0, 0);

    for (int it = 0; it < NIT; it++) {
        if (it + 1 < NIT) { ISSUE((it+1)&1, (it+1)*BK); CP_WAIT1; }
        else              { CP_WAIT0; }
        __syncthreads();
        uint32_t sA = sb + (it&1)*STAGE;
        uint32_t sB = sA + STG;
        #pragma unroll
        for (int ks = 0; ks < 2; ks++) {
            uint32_t a[2][4];
            #pragma unroll
            for (int i = 0; i < 2; i++)
                ldsm4(a[i], sA + (uint32_t)(wm + i*16)*PITCHB + ks*32 + lmoff);
            #pragma unroll
            for (int jp = 0; jp < 4; jp++) {
                uint32_t b[4];
                ldsm4(b, sB + (uint32_t)(bn0 + jp*16)*PITCHB + ks*32 + lmoff);
                mma_f16(acc[0][2*jp  ], a[0], b[0], b[2]);
                mma_f16(acc[1][2*jp  ], a[1], b[0], b[2]);
                mma_f16(acc[0][2*jp+1], a[0], b[1], b[3]);
                mma_f16(acc[1][2*jp+1], a[1], b[1], b[3]);
            }
        }
        __syncthreads();
    }

    #pragma unroll
    for (int i = 0; i < 2; i++) {
        #pragma unroll
        for (int h = 0; h < 2; h++) {
            int rl = (wid & 3)*32 + i*16 + gid + h*8;
            int r = row0 + rl;
            if (r >= ne) continue;
            int p = n0 + r;
            float w = g_wt[p];
            float* dst = g_outp + (size_t)g_slot[p] * NH + col0 + bn0;
            #pragma unroll
            for (int j = 0; j < 8; j++) {
                float v0 = w * acc[i][j][h*2];
                float v1 = w * acc[i][j][h*2+1];
                *(float2*)&dst[j*8 + 2*tig] = make_float2(v0, v1);
            }
        }
    }
}

// ---------------------------------------------------------------------------
// Deterministic per-token reduction over the 4 slots (fixed order).
// ---------------------------------------------------------------------------
__global__ void reduce_kernel(float* __restrict__ out) {
    int idx4 = blockIdx.x * blockDim.x + threadIdx.x;
    if (idx4 >= NT * NH / 4) return;
    int t  = idx4 / (NH/4);
    int h4 = idx4 % (NH/4);
    float4 s = make_float4(0.f, 0.f, 0.f, 0.f);
    #pragma unroll
    for (int k = 0; k < NK; k++) {
        const float4 v = *(const float4*)&g_outp[(size_t)(t*NK + k) * NH + h4*4];
        s.x += v.x; s.y += v.y; s.z += v.z; s.w += v.w;
    }
    *(float4*)&out[(size_t)t * NH + h4*4] = s;
}

// ---------------------------------------------------------------------------
extern "C" void kernel_launch(void* const* d_in, const int* in_sizes, int n_in,
                              void* d_out, int out_size)
{
    const float* X    = (const float*)d_in[0];
    const int*   idx  = (const int*)  d_in[1];
    const float* tw   = (const float*)d_in[2];
    const float* gup  = (const float*)d_in[3];
    const float* down = (const float*)d_in[4];
    float* out = (float*)d_out;

    __half* dXh; __half* dGh; __half* dDh;
    cudaGetSymbolAddress((void**)&dXh, g_Xh);
    cudaGetSymbolAddress((void**)&dGh, g_guph);
    cudaGetSymbolAddress((void**)&dDh, g_downh);

    int n1 = NE*2*NI*NH/8, n2 = NE*NH*NI/8, n3 = NT*NH/8;
    cvt_kernel<<<(n1+255)/256, 256>>>((const float4*)gup,  (uint4*)dGh, n1);
    cvt_kernel<<<(n2+255)/256, 256>>>((const float4*)down, (uint4*)dDh, n2);
    cvt_kernel<<<(n3+255)/256, 256>>>((const float4*)X,    (uint4*)dXh, n3);
    route_kernel<<<1, 256>>>(idx, tw);

    gemm1_kernel<<<dim3(NI/64,  MAXT), 256>>>();
    gemm2_kernel<<<dim3(NH/128, MAXT), 256>>>();
    reduce_kernel<<<(NT*NH/4 + 255)/256, 256>>>(out);
}

// round 16
// speedup vs baseline: 1.3416x; 1.0638x over previous
#include <cuda_runtime.h>
#include <cuda_fp16.h>
#include <math.h>
#include <stdint.h>

// Problem constants
#define NE 32
#define NT 2048
#define NH 1024
#define NI 512
#define NK 4
#define NP (NT*NK)   // 8192 routed pairs

#define BM 128
#define BK 32
#define MAXT 96
#define NS 3

#define PITCHB 80                    // bytes per smem row (64B data + 16B pad)
#define STG    (BM*PITCHB)           // 10240 B per operand tile
#define STAGE  (2*STG)               // A+B per stage = 20480 B
#define SMEM_BYTES (NS*STAGE)        // 61440 B (3 stages); epilogue reuses it

// ---- scratch (device globals) ----
__device__ int g_off[NE+1];
__device__ int g_tok[NP];
__device__ int g_slot[NP];
__device__ float g_wt[NP];
__device__ int g_tile_e[MAXT];
__device__ int g_tile_r[MAXT];
__device__ int g_ntile;
__device__ __align__(16) __half g_Xh[(size_t)NT*NH];          // 4 MB
__device__ __align__(16) __half g_guph[(size_t)NE*2*NI*NH];   // 64 MB
__device__ __align__(16) __half g_downh[(size_t)NE*NH*NI];    // 32 MB
__device__ __align__(16) __half g_hh[(size_t)NP*NI];          // 8 MB
__device__ __align__(16) float  g_outp[(size_t)NP*NH];        // 32 MB

// ---------------- PTX helpers ----------------
__device__ __forceinline__ void ldsm4(uint32_t* r, uint32_t a) {
    asm volatile("ldmatrix.sync.aligned.m8n8.x4.shared.b16 {%0,%1,%2,%3}, [%4];"
        : "=r"(r[0]), "=r"(r[1]), "=r"(r[2]), "=r"(r[3]) : "r"(a));
}
__device__ __forceinline__ void mma_f16(float c[4], const uint32_t a[4],
                                        uint32_t b0, uint32_t b1) {
    asm volatile(
        "mma.sync.aligned.m16n8k16.row.col.f32.f16.f16.f32 "
        "{%0,%1,%2,%3}, {%4,%5,%6,%7}, {%8,%9}, {%0,%1,%2,%3};\n"
        : "+f"(c[0]), "+f"(c[1]), "+f"(c[2]), "+f"(c[3])
        : "r"(a[0]), "r"(a[1]), "r"(a[2]), "r"(a[3]), "r"(b0), "r"(b1));
}
__device__ __forceinline__ void cp16(uint32_t smem_addr, const void* gmem) {
    asm volatile("cp.async.cg.shared.global [%0], [%1], 16;\n" :: "r"(smem_addr), "l"(gmem));
}
#define CP_COMMIT asm volatile("cp.async.commit_group;\n")
#define CP_WAIT1  asm volatile("cp.async.wait_group 1;\n" ::: "memory")
#define CP_WAIT0  asm volatile("cp.async.wait_group 0;\n" ::: "memory")
__device__ __forceinline__ uint32_t s2u(const void* p) {
    uint32_t a; asm("{ .reg .u64 t; cvta.to.shared.u64 t, %1; cvt.u32.u64 %0, t; }"
                    : "=r"(a) : "l"(p)); return a;
}
__device__ __forceinline__ uint32_t h2_bits(__half2 h) {
    union { __half2 h; uint32_t u; } c; c.h = h; return c.u;
}

// ---------------- fp32 -> fp16 conversion (rn) ----------------
__global__ void cvt_kernel(const float4* __restrict__ src, uint4* __restrict__ dst, int n8) {
    int i = blockIdx.x * blockDim.x + threadIdx.x;
    if (i >= n8) return;
    float4 v0 = src[2*i], v1 = src[2*i+1];
    uint4 o;
    o.x = h2_bits(__floats2half2_rn(v0.x, v0.y));
    o.y = h2_bits(__floats2half2_rn(v0.z, v0.w));
    o.z = h2_bits(__floats2half2_rn(v1.x, v1.y));
    o.w = h2_bits(__floats2half2_rn(v1.z, v1.w));
    dst[i] = o;
}

// ---------------- routing: smem-atomic counting sort (1 block, 1024 thr) ----
__global__ __launch_bounds__(1024) void route_kernel(
    const int* __restrict__ idx, const float* __restrict__ tw)
{
    __shared__ int scnt[NE], scur[NE], soff[NE];
    int tid = threadIdx.x;
    if (tid < NE) { scnt[tid] = 0; scur[tid] = 0; }
    __syncthreads();
    int myi[NP/1024]; int mye[NP/1024];
    #pragma unroll
    for (int j = 0; j < NP/1024; j++) {
        int i = tid + j*1024;
        myi[j] = i; mye[j] = idx[i];
        atomicAdd(&scnt[mye[j]], 1);
    }
    __syncthreads();
    if (tid == 0) {
        int s = 0, nt = 0;
        for (int e = 0; e < NE; e++) {
            soff[e] = s; g_off[e] = s;
            int c = scnt[e];
            for (int r0 = 0; r0 < c; r0 += BM) { g_tile_e[nt] = e; g_tile_r[nt] = r0; nt++; }
            s += c;
        }
        g_off[NE] = s;
        g_ntile = nt;
    }
    __syncthreads();
    #pragma unroll
    for (int j = 0; j < NP/1024; j++) {
        int i = myi[j], e = mye[j];
        int p = soff[e] + atomicAdd(&scur[e], 1);
        g_tok[p]  = i >> 2;
        g_slot[p] = i;
        g_wt[p]   = tw[i];
    }
}

// ---------------------------------------------------------------------------
// GEMM1 (fp16 mma.sync m16n8k16 + ldmatrix): 128 rows x [64 gate | 64 up].
// 3-stage cp.async pipeline, ONE __syncthreads per K-tile.
// ---------------------------------------------------------------------------
__global__ __launch_bounds__(256, 2) void gemm1_kernel(void)
{
    int by = blockIdx.y;
    if (by >= g_ntile) return;
    extern __shared__ __align__(16) uint8_t smem[];

    int e = g_tile_e[by], row0 = g_tile_r[by];
    int n0 = g_off[e], ne = g_off[e+1] - n0;
    int col0 = blockIdx.x * 64;

    uint32_t sb = s2u(smem);
    int tid = threadIdx.x;
    int wid = tid >> 5, lane = tid & 31;

    // loaders: tid<128 -> A (token rows), tid>=128 -> B (64 gate + 64 up rows)
    bool isB = tid >= 128;
    int lrow = tid & 127;
    const __half* lsrc;
    if (!isB) {
        int rr = row0 + lrow;
        int tok = g_tok[n0 + (rr < ne ? rr : 0)];
        lsrc = g_Xh + (size_t)tok * NH;
    } else {
        const __half* Wg = g_guph + (size_t)e * (2*NI) * NH;
        lsrc = (lrow < 64) ? Wg + (size_t)(col0 + lrow) * NH
                           : Wg + (size_t)(NI + col0 + (lrow - 64)) * NH;
    }
    uint32_t ldst = sb + (isB ? STG : 0) + (uint32_t)lrow * PITCHB;

    #define ISSUE(s, kk) do { \
        uint32_t d = ldst + (s)*STAGE; \
        const __half* p = lsrc + (kk); \
        cp16(d,      p); cp16(d+16, p+8); cp16(d+32, p+16); cp16(d+48, p+24); \
        CP_COMMIT; \
    } while (0)

    int wm = (wid & 3) * 32;          // warp M offset
    int half = wid >> 2;              // 0 = gate cols, 1 = up cols
    int bn0 = half * 64;              // B smem row base for this warp
    int gid = lane >> 2, tig = lane & 3;
    uint32_t lmoff = (uint32_t)(lane & 15) * PITCHB + (uint32_t)(lane >> 4) * 16;

    float acc[2][8][4] = {};

    const int NIT = NH / BK;   // 32
    ISSUE(0, 0);
    ISSUE(1, BK);

    int sc = 0, sl = 2;
    for (int it = 0; it < NIT; it++) {
        if (it + 1 < NIT) { CP_WAIT1; } else { CP_WAIT0; }
        __syncthreads();
        // safe: stage sl == (it-1)%NS, fully read in iter it-1 (all warps past barrier)
        if (it + 2 < NIT) {
            ISSUE(sl, (it+2)*BK);
            if (++sl == NS) sl = 0;
        }
        uint32_t sA = sb + sc*STAGE;
        uint32_t sB = sA + STG;
        #pragma unroll
        for (int ks = 0; ks < 2; ks++) {
            uint32_t a[2][4];
            #pragma unroll
            for (int i = 0; i < 2; i++)
                ldsm4(a[i], sA + (uint32_t)(wm + i*16)*PITCHB + ks*32 + lmoff);
            #pragma unroll
            for (int jp = 0; jp < 4; jp++) {
                uint32_t b[4];
                ldsm4(b, sB + (uint32_t)(bn0 + jp*16)*PITCHB + ks*32 + lmoff);
                mma_f16(acc[0][2*jp  ], a[0], b[0], b[2]);
                mma_f16(acc[1][2*jp  ], a[1], b[0], b[2]);
                mma_f16(acc[0][2*jp+1], a[0], b[1], b[3]);
                mma_f16(acc[1][2*jp+1], a[1], b[1], b[3]);
            }
        }
        if (++sc == NS) sc = 0;
    }
    __syncthreads();   // before smem reuse as exchange buffer

    // Epilogue: exchange up-half via smem, gate warps compute silu(g)*u -> g_hh
    float* ex = (float*)smem;          // 128 x 66 floats = 33.8 KB (< 60 KB)
    if (half == 1) {
        #pragma unroll
        for (int i = 0; i < 2; i++) {
            int rb = (wid & 3)*32 + i*16 + gid;
            #pragma unroll
            for (int j = 0; j < 8; j++) {
                ex[(rb  )*66 + j*8 + 2*tig    ] = acc[i][j][0];
                ex[(rb  )*66 + j*8 + 2*tig + 1] = acc[i][j][1];
                ex[(rb+8)*66 + j*8 + 2*tig    ] = acc[i][j][2];
                ex[(rb+8)*66 + j*8 + 2*tig + 1] = acc[i][j][3];
            }
        }
    }
    __syncthreads();
    if (half == 0) {
        #pragma unroll
        for (int i = 0; i < 2; i++) {
            #pragma unroll
            for (int h = 0; h < 2; h++) {
                int rl = (wid & 3)*32 + i*16 + gid + h*8;
                int r = row0 + rl;
                if (r >= ne) continue;
                __half* dst = g_hh + (size_t)(n0 + r) * NI + col0;
                #pragma unroll
                for (int j = 0; j < 8; j++) {
                    float g0 = acc[i][j][h*2],   u0 = ex[rl*66 + j*8 + 2*tig];
                    float g1 = acc[i][j][h*2+1], u1 = ex[rl*66 + j*8 + 2*tig + 1];
                    float v0 = g0 / (1.f + __expf(-g0)) * u0;
                    float v1 = g1 / (1.f + __expf(-g1)) * u1;
                    *(__half2*)&dst[j*8 + 2*tig] = __floats2half2_rn(v0, v1);
                }
            }
        }
    }
}

// ---------------------------------------------------------------------------
// GEMM2 (fp16): h @ down^T, 128 rows x 128 H cols, scaled, slot-scattered.
// ---------------------------------------------------------------------------
__global__ __launch_bounds__(256, 2) void gemm2_kernel(void)
{
    int by = blockIdx.y;
    if (by >= g_ntile) return;
    extern __shared__ __align__(16) uint8_t smem[];

    int e = g_tile_e[by], row0 = g_tile_r[by];
    int n0 = g_off[e], ne = g_off[e+1] - n0;
    int col0 = blockIdx.x * 128;

    uint32_t sb = s2u(smem);
    int tid = threadIdx.x;
    int wid = tid >> 5, lane = tid & 31;

    bool isB = tid >= 128;
    int lrow = tid & 127;
    const __half* lsrc;
    if (!isB) {
        int rr = row0 + lrow;
        lsrc = g_hh + (size_t)(n0 + (rr < ne ? rr : 0)) * NI;
    } else {
        lsrc = g_downh + (size_t)e * NH * NI + (size_t)(col0 + lrow) * NI;
    }
    uint32_t ldst = sb + (isB ? STG : 0) + (uint32_t)lrow * PITCHB;

    int wm = (wid & 3) * 32;
    int bn0 = (wid >> 2) * 64;
    int gid = lane >> 2, tig = lane & 3;
    uint32_t lmoff = (uint32_t)(lane & 15) * PITCHB + (uint32_t)(lane >> 4) * 16;

    float acc[2][8][4] = {};

    const int NIT = NI / BK;   // 16
    ISSUE(0, 0);
    ISSUE(1, BK);

    int sc = 0, sl = 2;
    for (int it = 0; it < NIT; it++) {
        if (it + 1 < NIT) { CP_WAIT1; } else { CP_WAIT0; }
        __syncthreads();
        if (it + 2 < NIT) {
            ISSUE(sl, (it+2)*BK);
            if (++sl == NS) sl = 0;
        }
        uint32_t sA = sb + sc*STAGE;
        uint32_t sB = sA + STG;
        #pragma unroll
        for (int ks = 0; ks < 2; ks++) {
            uint32_t a[2][4];
            #pragma unroll
            for (int i = 0; i < 2; i++)
                ldsm4(a[i], sA + (uint32_t)(wm + i*16)*PITCHB + ks*32 + lmoff);
            #pragma unroll
            for (int jp = 0; jp < 4; jp++) {
                uint32_t b[4];
                ldsm4(b, sB + (uint32_t)(bn0 + jp*16)*PITCHB + ks*32 + lmoff);
                mma_f16(acc[0][2*jp  ], a[0], b[0], b[2]);
                mma_f16(acc[1][2*jp  ], a[1], b[0], b[2]);
                mma_f16(acc[0][2*jp+1], a[0], b[1], b[3]);
                mma_f16(acc[1][2*jp+1], a[1], b[1], b[3]);
            }
        }
        if (++sc == NS) sc = 0;
    }

    #pragma unroll
    for (int i = 0; i < 2; i++) {
        #pragma unroll
        for (int h = 0; h < 2; h++) {
            int rl = (wid & 3)*32 + i*16 + gid + h*8;
            int r = row0 + rl;
            if (r >= ne) continue;
            int p = n0 + r;
            float w = g_wt[p];
            float* dst = g_outp + (size_t)g_slot[p] * NH + col0 + bn0;
            #pragma unroll
            for (int j = 0; j < 8; j++) {
                float v0 = w * acc[i][j][h*2];
                float v1 = w * acc[i][j][h*2+1];
                *(float2*)&dst[j*8 + 2*tig] = make_float2(v0, v1);
            }
        }
    }
}

// ---------------------------------------------------------------------------
// Deterministic per-token reduction over the 4 slots (fixed order).
// ---------------------------------------------------------------------------
__global__ void reduce_kernel(float* __restrict__ out) {
    int idx4 = blockIdx.x * blockDim.x + threadIdx.x;
    if (idx4 >= NT * NH / 4) return;
    int t  = idx4 / (NH/4);
    int h4 = idx4 % (NH/4);
    float4 s = make_float4(0.f, 0.f, 0.f, 0.f);
    #pragma unroll
    for (int k = 0; k < NK; k++) {
        const float4 v = *(const float4*)&g_outp[(size_t)(t*NK + k) * NH + h4*4];
        s.x += v.x; s.y += v.y; s.z += v.z; s.w += v.w;
    }
    *(float4*)&out[(size_t)t * NH + h4*4] = s;
}

// ---------------------------------------------------------------------------
extern "C" void kernel_launch(void* const* d_in, const int* in_sizes, int n_in,
                              void* d_out, int out_size)
{
    const float* X    = (const float*)d_in[0];
    const int*   idx  = (const int*)  d_in[1];
    const float* tw   = (const float*)d_in[2];
    const float* gup  = (const float*)d_in[3];
    const float* down = (const float*)d_in[4];
    float* out = (float*)d_out;

    cudaFuncSetAttribute(gemm1_kernel, cudaFuncAttributeMaxDynamicSharedMemorySize, SMEM_BYTES);
    cudaFuncSetAttribute(gemm2_kernel, cudaFuncAttributeMaxDynamicSharedMemorySize, SMEM_BYTES);

    __half* dXh; __half* dGh; __half* dDh;
    cudaGetSymbolAddress((void**)&dXh, g_Xh);
    cudaGetSymbolAddress((void**)&dGh, g_guph);
    cudaGetSymbolAddress((void**)&dDh, g_downh);

    int n1 = NE*2*NI*NH/8, n2 = NE*NH*NI/8, n3 = NT*NH/8;
    cvt_kernel<<<(n1+255)/256, 256>>>((const float4*)gup,  (uint4*)dGh, n1);
    cvt_kernel<<<(n2+255)/256, 256>>>((const float4*)down, (uint4*)dDh, n2);
    cvt_kernel<<<(n3+255)/256, 256>>>((const float4*)X,    (uint4*)dXh, n3);
    route_kernel<<<1, 1024>>>(idx, tw);

    gemm1_kernel<<<dim3(NI/64,  MAXT), 256, SMEM_BYTES>>>();
    gemm2_kernel<<<dim3(NH/128, MAXT), 256, SMEM_BYTES>>>();
    reduce_kernel<<<(NT*NH/4 + 255)/256, 256>>>(out);
}

// round 17
// speedup vs baseline: 1.4214x; 1.0595x over previous
#include <cuda_runtime.h>
#include <cuda_fp16.h>
#include <math.h>
#include <stdint.h>

// Problem constants
#define NE 32
#define NT 2048
#define NH 1024
#define NI 512
#define NK 4
#define NP (NT*NK)   // 8192 routed pairs

#define BM 128
#define BK 32
#define MAXT 96
#define NS 3

#define PITCHB 80                    // bytes per smem row (64B data + 16B pad)
#define STG    (BM*PITCHB)           // 10240 B per operand tile
#define STAGE  (2*STG)               // A+B per stage = 20480 B
#define SMEM_BYTES (NS*STAGE)        // 61440 B (3 stages); epilogue reuses it

// ---- scratch (device globals) ----
__device__ int g_off[NE+1];
__device__ int g_tok[NP];
__device__ int g_slot[NP];
__device__ float g_wt[NP];
__device__ int g_tile_e[MAXT];
__device__ int g_tile_r[MAXT];
__device__ int g_ntile;
__device__ __align__(16) __half g_Xh[(size_t)NT*NH];          // 4 MB
__device__ __align__(16) __half g_guph[(size_t)NE*2*NI*NH];   // 64 MB
__device__ __align__(16) __half g_downh[(size_t)NE*NH*NI];    // 32 MB
__device__ __align__(16) __half g_hh[(size_t)NP*NI];          // 8 MB
__device__ __align__(16) float  g_outp[(size_t)NP*NH];        // 32 MB

// ---------------- PTX helpers ----------------
__device__ __forceinline__ void ldsm4(uint32_t* r, uint32_t a) {
    asm volatile("ldmatrix.sync.aligned.m8n8.x4.shared.b16 {%0,%1,%2,%3}, [%4];"
        : "=r"(r[0]), "=r"(r[1]), "=r"(r[2]), "=r"(r[3]) : "r"(a));
}
__device__ __forceinline__ void mma_f16(float c[4], const uint32_t a[4],
                                        uint32_t b0, uint32_t b1) {
    asm volatile(
        "mma.sync.aligned.m16n8k16.row.col.f32.f16.f16.f32 "
        "{%0,%1,%2,%3}, {%4,%5,%6,%7}, {%8,%9}, {%0,%1,%2,%3};\n"
        : "+f"(c[0]), "+f"(c[1]), "+f"(c[2]), "+f"(c[3])
        : "r"(a[0]), "r"(a[1]), "r"(a[2]), "r"(a[3]), "r"(b0), "r"(b1));
}
__device__ __forceinline__ void cp16(uint32_t smem_addr, const void* gmem) {
    asm volatile("cp.async.cg.shared.global [%0], [%1], 16;\n" :: "r"(smem_addr), "l"(gmem));
}
#define CP_COMMIT asm volatile("cp.async.commit_group;\n")
#define CP_WAIT1  asm volatile("cp.async.wait_group 1;\n" ::: "memory")
#define CP_WAIT0  asm volatile("cp.async.wait_group 0;\n" ::: "memory")
__device__ __forceinline__ uint32_t s2u(const void* p) {
    uint32_t a; asm("{ .reg .u64 t; cvta.to.shared.u64 t, %1; cvt.u32.u64 %0, t; }"
                    : "=r"(a) : "l"(p)); return a;
}
__device__ __forceinline__ uint32_t h2_bits(__half2 h) {
    union { __half2 h; uint32_t u; } c; c.h = h; return c.u;
}

// ---------------- fp32 -> fp16 conversion (rn) ----------------
__global__ void cvt_kernel(const float4* __restrict__ src, uint4* __restrict__ dst, int n8) {
    int i = blockIdx.x * blockDim.x + threadIdx.x;
    if (i >= n8) return;
    float4 v0 = src[2*i], v1 = src[2*i+1];
    uint4 o;
    o.x = h2_bits(__floats2half2_rn(v0.x, v0.y));
    o.y = h2_bits(__floats2half2_rn(v0.z, v0.w));
    o.z = h2_bits(__floats2half2_rn(v1.x, v1.y));
    o.w = h2_bits(__floats2half2_rn(v1.z, v1.w));
    dst[i] = o;
}

// ---------------- routing: smem-atomic counting sort (1 block, 1024 thr) ----
__global__ __launch_bounds__(1024) void route_kernel(
    const int* __restrict__ idx, const float* __restrict__ tw)
{
    __shared__ int scnt[NE], scur[NE], soff[NE];
    int tid = threadIdx.x;
    if (tid < NE) { scnt[tid] = 0; scur[tid] = 0; }
    __syncthreads();
    int myi[NP/1024]; int mye[NP/1024];
    #pragma unroll
    for (int j = 0; j < NP/1024; j++) {
        int i = tid + j*1024;
        myi[j] = i; mye[j] = idx[i];
        atomicAdd(&scnt[mye[j]], 1);
    }
    __syncthreads();
    if (tid == 0) {
        int s = 0, nt = 0;
        for (int e = 0; e < NE; e++) {
            soff[e] = s; g_off[e] = s;
            int c = scnt[e];
            for (int r0 = 0; r0 < c; r0 += BM) { g_tile_e[nt] = e; g_tile_r[nt] = r0; nt++; }
            s += c;
        }
        g_off[NE] = s;
        g_ntile = nt;
    }
    __syncthreads();
    #pragma unroll
    for (int j = 0; j < NP/1024; j++) {
        int i = myi[j], e = mye[j];
        int p = soff[e] + atomicAdd(&scur[e], 1);
        g_tok[p]  = i >> 2;
        g_slot[p] = i;
        g_wt[p]   = tw[i];
    }
}

// ---------------------------------------------------------------------------
// GEMM1 (fp16 mma.sync m16n8k16 + ldmatrix): 128 rows x [64 gate | 64 up].
// 3-stage cp.async pipeline, ONE __syncthreads per K-tile.
// ---------------------------------------------------------------------------
__global__ __launch_bounds__(256, 2) void gemm1_kernel(void)
{
    int by = blockIdx.y;
    if (by >= g_ntile) return;
    extern __shared__ __align__(16) uint8_t smem[];

    int e = g_tile_e[by], row0 = g_tile_r[by];
    int n0 = g_off[e], ne = g_off[e+1] - n0;
    int col0 = blockIdx.x * 64;

    uint32_t sb = s2u(smem);
    int tid = threadIdx.x;
    int wid = tid >> 5, lane = tid & 31;

    // loaders: tid<128 -> A (token rows), tid>=128 -> B (64 gate + 64 up rows)
    bool isB = tid >= 128;
    int lrow = tid & 127;
    const __half* lsrc;
    if (!isB) {
        int rr = row0 + lrow;
        int tok = g_tok[n0 + (rr < ne ? rr : 0)];
        lsrc = g_Xh + (size_t)tok * NH;
    } else {
        const __half* Wg = g_guph + (size_t)e * (2*NI) * NH;
        lsrc = (lrow < 64) ? Wg + (size_t)(col0 + lrow) * NH
                           : Wg + (size_t)(NI + col0 + (lrow - 64)) * NH;
    }
    uint32_t ldst = sb + (isB ? STG : 0) + (uint32_t)lrow * PITCHB;

    #define ISSUE(s, kk) do { \
        uint32_t d = ldst + (s)*STAGE; \
        const __half* p = lsrc + (kk); \
        cp16(d,      p); cp16(d+16, p+8); cp16(d+32, p+16); cp16(d+48, p+24); \
        CP_COMMIT; \
    } while (0)

    int wm = (wid & 3) * 32;          // warp M offset
    int half = wid >> 2;              // 0 = gate cols, 1 = up cols
    int bn0 = half * 64;              // B smem row base for this warp
    int gid = lane >> 2, tig = lane & 3;
    uint32_t lmoff = (uint32_t)(lane & 15) * PITCHB + (uint32_t)(lane >> 4) * 16;

    float acc[2][8][4] = {};

    const int NIT = NH / BK;   // 32
    ISSUE(0, 0);
    ISSUE(1, BK);

    int sc = 0, sl = 2;
    for (int it = 0; it < NIT; it++) {
        if (it + 1 < NIT) { CP_WAIT1; } else { CP_WAIT0; }
        __syncthreads();
        // safe: stage sl == (it-1)%NS, fully read in iter it-1 (all warps past barrier)
        if (it + 2 < NIT) {
            ISSUE(sl, (it+2)*BK);
            if (++sl == NS) sl = 0;
        }
        uint32_t sA = sb + sc*STAGE;
        uint32_t sB = sA + STG;
        #pragma unroll
        for (int ks = 0; ks < 2; ks++) {
            uint32_t a[2][4];
            #pragma unroll
            for (int i = 0; i < 2; i++)
                ldsm4(a[i], sA + (uint32_t)(wm + i*16)*PITCHB + ks*32 + lmoff);
            #pragma unroll
            for (int jp = 0; jp < 4; jp++) {
                uint32_t b[4];
                ldsm4(b, sB + (uint32_t)(bn0 + jp*16)*PITCHB + ks*32 + lmoff);
                mma_f16(acc[0][2*jp  ], a[0], b[0], b[2]);
                mma_f16(acc[1][2*jp  ], a[1], b[0], b[2]);
                mma_f16(acc[0][2*jp+1], a[0], b[1], b[3]);
                mma_f16(acc[1][2*jp+1], a[1], b[1], b[3]);
            }
        }
        if (++sc == NS) sc = 0;
    }
    __syncthreads();   // before smem reuse as exchange buffer

    // Epilogue: exchange up-half via smem, gate warps compute silu(g)*u -> g_hh
    float* ex = (float*)smem;          // 128 x 66 floats = 33.8 KB (< 60 KB)
    if (half == 1) {
        #pragma unroll
        for (int i = 0; i < 2; i++) {
            int rb = (wid & 3)*32 + i*16 + gid;
            #pragma unroll
            for (int j = 0; j < 8; j++) {
                ex[(rb  )*66 + j*8 + 2*tig    ] = acc[i][j][0];
                ex[(rb  )*66 + j*8 + 2*tig + 1] = acc[i][j][1];
                ex[(rb+8)*66 + j*8 + 2*tig    ] = acc[i][j][2];
                ex[(rb+8)*66 + j*8 + 2*tig + 1] = acc[i][j][3];
            }
        }
    }
    __syncthreads();
    if (half == 0) {
        #pragma unroll
        for (int i = 0; i < 2; i++) {
            #pragma unroll
            for (int h = 0; h < 2; h++) {
                int rl = (wid & 3)*32 + i*16 + gid + h*8;
                int r = row0 + rl;
                if (r >= ne) continue;
                __half* dst = g_hh + (size_t)(n0 + r) * NI + col0;
                #pragma unroll
                for (int j = 0; j < 8; j++) {
                    float g0 = acc[i][j][h*2],   u0 = ex[rl*66 + j*8 + 2*tig];
                    float g1 = acc[i][j][h*2+1], u1 = ex[rl*66 + j*8 + 2*tig + 1];
                    float v0 = g0 / (1.f + __expf(-g0)) * u0;
                    float v1 = g1 / (1.f + __expf(-g1)) * u1;
                    *(__half2*)&dst[j*8 + 2*tig] = __floats2half2_rn(v0, v1);
                }
            }
        }
    }
}

// ---------------------------------------------------------------------------
// GEMM2 (fp16): h @ down^T, 128 rows x 128 H cols, scaled, slot-scattered.
// ---------------------------------------------------------------------------
__global__ __launch_bounds__(256, 2) void gemm2_kernel(void)
{
    int by = blockIdx.y;
    if (by >= g_ntile) return;
    extern __shared__ __align__(16) uint8_t smem[];

    int e = g_tile_e[by], row0 = g_tile_r[by];
    int n0 = g_off[e], ne = g_off[e+1] - n0;
    int col0 = blockIdx.x * 128;

    uint32_t sb = s2u(smem);
    int tid = threadIdx.x;
    int wid = tid >> 5, lane = tid & 31;

    bool isB = tid >= 128;
    int lrow = tid & 127;
    const __half* lsrc;
    if (!isB) {
        int rr = row0 + lrow;
        lsrc = g_hh + (size_t)(n0 + (rr < ne ? rr : 0)) * NI;
    } else {
        lsrc = g_downh + (size_t)e * NH * NI + (size_t)(col0 + lrow) * NI;
    }
    uint32_t ldst = sb + (isB ? STG : 0) + (uint32_t)lrow * PITCHB;

    int wm = (wid & 3) * 32;
    int bn0 = (wid >> 2) * 64;
    int gid = lane >> 2, tig = lane & 3;
    uint32_t lmoff = (uint32_t)(lane & 15) * PITCHB + (uint32_t)(lane >> 4) * 16;

    float acc[2][8][4] = {};

    const int NIT = NI / BK;   // 16
    ISSUE(0, 0);
    ISSUE(1, BK);

    int sc = 0, sl = 2;
    for (int it = 0; it < NIT; it++) {
        if (it + 1 < NIT) { CP_WAIT1; } else { CP_WAIT0; }
        __syncthreads();
        if (it + 2 < NIT) {
            ISSUE(sl, (it+2)*BK);
            if (++sl == NS) sl = 0;
        }
        uint32_t sA = sb + sc*STAGE;
        uint32_t sB = sA + STG;
        #pragma unroll
        for (int ks = 0; ks < 2; ks++) {
            uint32_t a[2][4];
            #pragma unroll
            for (int i = 0; i < 2; i++)
                ldsm4(a[i], sA + (uint32_t)(wm + i*16)*PITCHB + ks*32 + lmoff);
            #pragma unroll
            for (int jp = 0; jp < 4; jp++) {
                uint32_t b[4];
                ldsm4(b, sB + (uint32_t)(bn0 + jp*16)*PITCHB + ks*32 + lmoff);
                mma_f16(acc[0][2*jp  ], a[0], b[0], b[2]);
                mma_f16(acc[1][2*jp  ], a[1], b[0], b[2]);
                mma_f16(acc[0][2*jp+1], a[0], b[1], b[3]);
                mma_f16(acc[1][2*jp+1], a[1], b[1], b[3]);
            }
        }
        if (++sc == NS) sc = 0;
    }

    #pragma unroll
    for (int i = 0; i < 2; i++) {
        #pragma unroll
        for (int h = 0; h < 2; h++) {
            int rl = (wid & 3)*32 + i*16 + gid + h*8;
            int r = row0 + rl;
            if (r >= ne) continue;
            int p = n0 + r;
            float w = g_wt[p];
            float* dst = g_outp + (size_t)g_slot[p] * NH + col0 + bn0;
            #pragma unroll
            for (int j = 0; j < 8; j++) {
                float v0 = w * acc[i][j][h*2];
                float v1 = w * acc[i][j][h*2+1];
                *(float2*)&dst[j*8 + 2*tig] = make_float2(v0, v1);
            }
        }
    }
}

// ---------------------------------------------------------------------------
// Deterministic per-token reduction over the 4 slots (fixed order).
// ---------------------------------------------------------------------------
__global__ void reduce_kernel(float* __restrict__ out) {
    int idx4 = blockIdx.x * blockDim.x + threadIdx.x;
    if (idx4 >= NT * NH / 4) return;
    int t  = idx4 / (NH/4);
    int h4 = idx4 % (NH/4);
    float4 s = make_float4(0.f, 0.f, 0.f, 0.f);
    #pragma unroll
    for (int k = 0; k < NK; k++) {
        const float4 v = *(const float4*)&g_outp[(size_t)(t*NK + k) * NH + h4*4];
        s.x += v.x; s.y += v.y; s.z += v.z; s.w += v.w;
    }
    *(float4*)&out[(size_t)t * NH + h4*4] = s;
}

// ---------------------------------------------------------------------------
// Launch: route and cvt_down forked onto side streams (graph branches) so
// their latency hides under cvt_gup / gemm1. Same work every call; streams
// and events are persistent host resources created on first (uncaptured) call.
// ---------------------------------------------------------------------------
extern "C" void kernel_launch(void* const* d_in, const int* in_sizes, int n_in,
                              void* d_out, int out_size)
{
    const float* X    = (const float*)d_in[0];
    const int*   idx  = (const int*)  d_in[1];
    const float* tw   = (const float*)d_in[2];
    const float* gup  = (const float*)d_in[3];
    const float* down = (const float*)d_in[4];
    float* out = (float*)d_out;

    static cudaStream_t s1 = nullptr, s2 = nullptr;
    static cudaEvent_t evF = nullptr, evJ1 = nullptr, evJ2 = nullptr;
    if (!s1) {
        cudaStreamCreateWithFlags(&s1, cudaStreamNonBlocking);
        cudaStreamCreateWithFlags(&s2, cudaStreamNonBlocking);
        cudaEventCreateWithFlags(&evF,  cudaEventDisableTiming);
        cudaEventCreateWithFlags(&evJ1, cudaEventDisableTiming);
        cudaEventCreateWithFlags(&evJ2, cudaEventDisableTiming);
        cudaFuncSetAttribute(gemm1_kernel, cudaFuncAttributeMaxDynamicSharedMemorySize, SMEM_BYTES);
        cudaFuncSetAttribute(gemm2_kernel, cudaFuncAttributeMaxDynamicSharedMemorySize, SMEM_BYTES);
    }

    __half* dXh; __half* dGh; __half* dDh;
    cudaGetSymbolAddress((void**)&dXh, g_Xh);
    cudaGetSymbolAddress((void**)&dGh, g_guph);
    cudaGetSymbolAddress((void**)&dDh, g_downh);

    int n1 = NE*2*NI*NH/8, n2 = NE*NH*NI/8, n3 = NT*NH/8;

    // fork
    cudaEventRecord(evF, 0);
    cudaStreamWaitEvent(s1, evF, 0);
    cudaStreamWaitEvent(s2, evF, 0);

    // side branch 1: routing (latency-bound, hides under cvt_gup)
    route_kernel<<<1, 1024, 0, s1>>>(idx, tw);
    cudaEventRecord(evJ1, s1);

    // side branch 2: down-proj conversion (only needed by gemm2)
    cvt_kernel<<<(n2+255)/256, 256, 0, s2>>>((const float4*)down, (uint4*)dDh, n2);
    cudaEventRecord(evJ2, s2);

    // main branch: gate_up + X conversion
    cvt_kernel<<<(n1+255)/256, 256>>>((const float4*)gup, (uint4*)dGh, n1);
    cvt_kernel<<<(n3+255)/256, 256>>>((const float4*)X,   (uint4*)dXh, n3);

    cudaStreamWaitEvent(0, evJ1, 0);
    gemm1_kernel<<<dim3(NI/64,  MAXT), 256, SMEM_BYTES>>>();
    cudaStreamWaitEvent(0, evJ2, 0);
    gemm2_kernel<<<dim3(NH/128, MAXT), 256, SMEM_BYTES>>>();
    reduce_kernel<<<(NT*NH/4 + 255)/256, 256>>>(out);
}